// round 6
// baseline (speedup 1.0000x reference)
#include <cuda_runtime.h>
#include <stdint.h>

// MessagePassing: out[dst[e]] += x[src[e]], N=100000, E=1600000, D=32 fp32.
// edge_index int32 [2, E]: row 0 = src, row 1 = dst.
//
// Binning pipeline (counting sort by dst, fixed capacity, no prefix scan):
//   A) cudaMemsetAsync out + counts
//   B) 4 edges/thread: p = atomicAdd(counts[d]); bins[d*32+p] = s
//      (RED fallback on overflow -> unconditional correctness)
//   C) 8 lanes per node: gather binned src rows (MLP=8), accumulate in regs,
//      one 128B store. Kills the 205MB RED atomic traffic of edge-centric.

#define D_FEAT    32
#define CHUNKS    8        // D_FEAT / 4
#define MAX_NODES 100000
#define BIN_CAP   32       // Poisson(16); ~20 nodes overflow -> RED fallback

__device__ int g_counts[MAX_NODES];
__device__ int g_bins[(long)MAX_NODES * BIN_CAP];

__device__ __forceinline__ void red_add_v4(float* p, float4 v) {
    asm volatile("red.global.add.v4.f32 [%0], {%1, %2, %3, %4};"
                 :: "l"(p), "f"(v.x), "f"(v.y), "f"(v.z), "f"(v.w)
                 : "memory");
}

__device__ __forceinline__ void bin_one(int s, int d, const float4* x, float* out) {
    int p = atomicAdd(&g_counts[d], 1);
    if (p < BIN_CAP) {
        g_bins[(long)d * BIN_CAP + p] = s;
    } else {
        #pragma unroll
        for (int c = 0; c < CHUNKS; ++c)
            red_add_v4(out + (long)d * D_FEAT + c * 4,
                       __ldg(&x[(long)s * CHUNKS + c]));
    }
}

// Phase B: bin edges by dst, 4 edges per thread.
__global__ void mp_bin_kernel(const float4* __restrict__ x,
                              const int* __restrict__ src,
                              const int* __restrict__ dst,
                              float* __restrict__ out,
                              long n_edges) {
    long t  = (long)blockIdx.x * blockDim.x + threadIdx.x;
    long e0 = t * 4;
    if (e0 >= n_edges) return;

    if (e0 + 4 <= n_edges) {
        int4 s = __ldg((const int4*)(src + e0));
        int4 d = __ldg((const int4*)(dst + e0));
        bin_one(s.x, d.x, x, out);
        bin_one(s.y, d.y, x, out);
        bin_one(s.z, d.z, x, out);
        bin_one(s.w, d.w, x, out);
    } else {
        for (long e = e0; e < n_edges; ++e)
            bin_one(__ldg(&src[e]), __ldg(&dst[e]), x, out);
    }
}

// Phase C: 8 lanes per node; lane c owns 16B chunk c. Gathers batched MLP=8.
__global__ void mp_gather_kernel(const float4* __restrict__ x,
                                 float4* __restrict__ out,
                                 int n_nodes) {
    long t = (long)blockIdx.x * blockDim.x + threadIdx.x;
    int n = (int)(t >> 3);
    int c = (int)(t & 7);
    if (n >= n_nodes) return;

    int k = __ldg(&g_counts[n]);
    if (k > BIN_CAP) k = BIN_CAP;

    long op = (long)n * CHUNKS + c;
    float4 acc = out[op];   // seeds with RED-fallback contributions (normally 0)

    const int* brow = g_bins + (long)n * BIN_CAP;
    int j = 0;
    // 8 gathers in flight.
    for (; j + 8 <= k; j += 8) {
        int4 sa = __ldg((const int4*)(brow + j));
        int4 sb = __ldg((const int4*)(brow + j + 4));
        float4 a0 = __ldg(&x[(long)sa.x * CHUNKS + c]);
        float4 a1 = __ldg(&x[(long)sa.y * CHUNKS + c]);
        float4 a2 = __ldg(&x[(long)sa.z * CHUNKS + c]);
        float4 a3 = __ldg(&x[(long)sa.w * CHUNKS + c]);
        float4 a4 = __ldg(&x[(long)sb.x * CHUNKS + c]);
        float4 a5 = __ldg(&x[(long)sb.y * CHUNKS + c]);
        float4 a6 = __ldg(&x[(long)sb.z * CHUNKS + c]);
        float4 a7 = __ldg(&x[(long)sb.w * CHUNKS + c]);
        acc.x += a0.x; acc.y += a0.y; acc.z += a0.z; acc.w += a0.w;
        acc.x += a1.x; acc.y += a1.y; acc.z += a1.z; acc.w += a1.w;
        acc.x += a2.x; acc.y += a2.y; acc.z += a2.z; acc.w += a2.w;
        acc.x += a3.x; acc.y += a3.y; acc.z += a3.z; acc.w += a3.w;
        acc.x += a4.x; acc.y += a4.y; acc.z += a4.z; acc.w += a4.w;
        acc.x += a5.x; acc.y += a5.y; acc.z += a5.z; acc.w += a5.w;
        acc.x += a6.x; acc.y += a6.y; acc.z += a6.z; acc.w += a6.w;
        acc.x += a7.x; acc.y += a7.y; acc.z += a7.z; acc.w += a7.w;
    }
    for (; j + 4 <= k; j += 4) {
        int4 sa = __ldg((const int4*)(brow + j));
        float4 a0 = __ldg(&x[(long)sa.x * CHUNKS + c]);
        float4 a1 = __ldg(&x[(long)sa.y * CHUNKS + c]);
        float4 a2 = __ldg(&x[(long)sa.z * CHUNKS + c]);
        float4 a3 = __ldg(&x[(long)sa.w * CHUNKS + c]);
        acc.x += a0.x; acc.y += a0.y; acc.z += a0.z; acc.w += a0.w;
        acc.x += a1.x; acc.y += a1.y; acc.z += a1.z; acc.w += a1.w;
        acc.x += a2.x; acc.y += a2.y; acc.z += a2.z; acc.w += a2.w;
        acc.x += a3.x; acc.y += a3.y; acc.z += a3.z; acc.w += a3.w;
    }
    for (; j < k; ++j) {
        int s = __ldg(&brow[j]);
        float4 a = __ldg(&x[(long)s * CHUNKS + c]);
        acc.x += a.x; acc.y += a.y; acc.z += a.z; acc.w += a.w;
    }
    out[op] = acc;
}

// Safety path (shape mismatch): edge-centric RED kernel.
__global__ void mp_scatter_kernel(const float4* __restrict__ x,
                                  const int* __restrict__ src,
                                  const int* __restrict__ dst,
                                  float* __restrict__ out,
                                  long n_edges) {
    long t = (long)blockIdx.x * blockDim.x + threadIdx.x;
    long e = t >> 3;
    int  c = (int)(t & 7);
    if (e >= n_edges) return;
    int s = __ldg(&src[e]);
    int d = __ldg(&dst[e]);
    float4 v = __ldg(&x[(long)s * CHUNKS + c]);
    red_add_v4(out + (long)d * D_FEAT + c * 4, v);
}

extern "C" void kernel_launch(void* const* d_in, const int* in_sizes, int n_in,
                              void* d_out, int out_size) {
    const float4* x   = (const float4*)d_in[0];
    const int*    ei  = (const int*)d_in[1];
    long n_edges = (long)in_sizes[1] / 2;
    const int* src = ei;
    const int* dst = ei + n_edges;
    float* out = (float*)d_out;
    int n_nodes = in_sizes[0] / D_FEAT;
    int threads = 256;

    // Phase A: zero out (+ counts) via memset nodes.
    cudaMemsetAsync(d_out, 0, (size_t)out_size * sizeof(float), 0);

    if (n_nodes > MAX_NODES) {
        // Shape-safety fallback: edge-centric RED path.
        long total = n_edges * CHUNKS;
        long blocks = (total + threads - 1) / threads;
        mp_scatter_kernel<<<(unsigned)blocks, threads>>>(x, src, dst, out, n_edges);
        return;
    }

    void* counts_ptr = nullptr;
    cudaGetSymbolAddress(&counts_ptr, g_counts);
    cudaMemsetAsync(counts_ptr, 0, (size_t)n_nodes * sizeof(int), 0);

    // Phase B: bin edges by dst (4 edges/thread).
    {
        long groups = (n_edges + 3) / 4;
        long blocks = (groups + threads - 1) / threads;
        mp_bin_kernel<<<(unsigned)blocks, threads>>>(x, src, dst, out, n_edges);
    }
    // Phase C: per-node gather-accumulate.
    {
        long total = (long)n_nodes * 8;
        long blocks = (total + threads - 1) / threads;
        mp_gather_kernel<<<(unsigned)blocks, threads>>>(x, (float4*)out, n_nodes);
    }
}